// round 1
// baseline (speedup 1.0000x reference)
#include <cuda_runtime.h>
#include <math.h>

#define BDIM 4
#define CDIM 64
#define IDIM 32
#define LDIM 4096

#define BM 128
#define BN 32

// scratch (allocation-free rule: __device__ globals)
__device__ float d_theta[BDIM * LDIM * IDIM];
__device__ float d_phi[BDIM * LDIM * IDIM];
__device__ float d_g[BDIM * LDIM * IDIM];
__device__ float d_y[BDIM * LDIM * IDIM];

// ---------------------------------------------------------------------------
// Kernel 1: channel projections  x[B,C,L] -> theta/phi/g  stored [B,L,32]
// ---------------------------------------------------------------------------
__global__ __launch_bounds__(256) void proj_kernel(
    const float* __restrict__ x,
    const float* __restrict__ g_w, const float* __restrict__ g_b,
    const float* __restrict__ th_w, const float* __restrict__ th_b,
    const float* __restrict__ ph_w, const float* __restrict__ ph_b)
{
    const int b  = blockIdx.y;
    const int l0 = blockIdx.x * 128;
    const int t  = threadIdx.x;

    __shared__ float xs[CDIM][128];       // x tile, [c][l]
    __shared__ float wsT[3][CDIM][IDIM];  // transposed weights [proj][c][o]
    __shared__ float bs[3][IDIM];

    const float* xb = x + (size_t)b * CDIM * LDIM + l0;
    for (int idx = t; idx < CDIM * 128; idx += 256) {
        int c = idx >> 7, l = idx & 127;
        xs[c][l] = xb[(size_t)c * LDIM + l];
    }
    for (int idx = t; idx < CDIM * IDIM; idx += 256) {
        int o = idx >> 6;   // idx = o*64 + c
        int c = idx & 63;
        wsT[0][c][o] = g_w[idx];
        wsT[1][c][o] = th_w[idx];
        wsT[2][c][o] = ph_w[idx];
    }
    if (t < IDIM) { bs[0][t] = g_b[t]; bs[1][t] = th_b[t]; bs[2][t] = ph_b[t]; }
    __syncthreads();

    const int o  = t & 31;
    const int lg = t >> 5;  // 0..7
    for (int i = 0; i < 16; ++i) {
        const int l = lg + (i << 3);
        float sg0 = 0.f, sg1 = 0.f, st0 = 0.f, st1 = 0.f, sp0 = 0.f, sp1 = 0.f;
#pragma unroll
        for (int c = 0; c < CDIM; c += 2) {
            float x0 = xs[c][l], x1 = xs[c + 1][l];
            sg0 = fmaf(wsT[0][c][o],     x0, sg0);
            sg1 = fmaf(wsT[0][c + 1][o], x1, sg1);
            st0 = fmaf(wsT[1][c][o],     x0, st0);
            st1 = fmaf(wsT[1][c + 1][o], x1, st1);
            sp0 = fmaf(wsT[2][c][o],     x0, sp0);
            sp1 = fmaf(wsT[2][c + 1][o], x1, sp1);
        }
        size_t oidx = ((size_t)b * LDIM + l0 + l) * IDIM + o;
        d_g[oidx]     = sg0 + sg1 + bs[0][o];
        d_theta[oidx] = st0 + st1 + bs[1][o];
        d_phi[oidx]   = sp0 + sp1 + bs[2][o];
    }
}

// ---------------------------------------------------------------------------
// Kernel 2: flash attention. softmax(theta . phi^T) @ g  -> y [B,L,32]
// 256 threads: threads 0..127 handle keys [0,2048), 128..255 handle [2048,4096)
// for the same 128 queries; partial softmax states merged at the end.
// ---------------------------------------------------------------------------
__global__ __launch_bounds__(256) void flash_kernel()
{
    const int b  = blockIdx.y;
    const int q0 = blockIdx.x * BM;
    const int t  = threadIdx.x;
    const int h  = t >> 7;    // key-half
    const int lt = t & 127;   // query index within tile

    __shared__ __align__(16) float4 Ks[2][BN][8];
    __shared__ __align__(16) float4 Vs[2][BN][8];
    __shared__ __align__(16) float4 stAcc[BM][9];  // padded (9) vs bank conflicts
    __shared__ float stM[BM];
    __shared__ float stL[BM];

    // load Q row into registers
    float4 q[8];
    const float4* Qp = (const float4*)(d_theta + ((size_t)b * LDIM + q0 + lt) * IDIM);
#pragma unroll
    for (int i = 0; i < 8; ++i) q[i] = Qp[i];

    float4 acc[8];
#pragma unroll
    for (int i = 0; i < 8; ++i) acc[i] = make_float4(0.f, 0.f, 0.f, 0.f);
    float m = -INFINITY, lsum = 0.f;

    const int HALFK = LDIM / 2;
    const float* Kb = d_phi + ((size_t)b * LDIM + (size_t)h * HALFK) * IDIM;
    const float* Vb = d_g   + ((size_t)b * LDIM + (size_t)h * HALFK) * IDIM;

    float4* KsH = (float4*)Ks[h];
    float4* VsH = (float4*)Vs[h];

    for (int kt = 0; kt < HALFK; kt += BN) {
        const float4* Kg = (const float4*)(Kb + (size_t)kt * IDIM);
        const float4* Vg = (const float4*)(Vb + (size_t)kt * IDIM);
        KsH[lt]       = Kg[lt];
        KsH[lt + 128] = Kg[lt + 128];
        VsH[lt]       = Vg[lt];
        VsH[lt + 128] = Vg[lt + 128];
        // barrier over this half's 4 warps only
        asm volatile("bar.sync %0, %1;" :: "r"(1 + h), "r"(128) : "memory");

        // ---- scores (fully unrolled: sc[] must stay in registers) ----
        float sc[BN];
#pragma unroll
        for (int j = 0; j < BN; ++j) {
            float s0 = 0.f, s1 = 0.f, s2 = 0.f, s3 = 0.f;
#pragma unroll
            for (int dd = 0; dd < 8; ++dd) {
                float4 kv = Ks[h][j][dd];
                s0 = fmaf(q[dd].x, kv.x, s0);
                s1 = fmaf(q[dd].y, kv.y, s1);
                s2 = fmaf(q[dd].z, kv.z, s2);
                s3 = fmaf(q[dd].w, kv.w, s3);
            }
            sc[j] = (s0 + s1) + (s2 + s3);
        }

        // ---- online softmax update ----
        float tmax = sc[0];
#pragma unroll
        for (int j = 1; j < BN; ++j) tmax = fmaxf(tmax, sc[j]);
        float mnew = fmaxf(m, tmax);
        float corr = __expf(m - mnew);
        m = mnew;
        lsum *= corr;
#pragma unroll
        for (int dd = 0; dd < 8; ++dd) {
            acc[dd].x *= corr; acc[dd].y *= corr;
            acc[dd].z *= corr; acc[dd].w *= corr;
        }
        float ps = 0.f;
#pragma unroll
        for (int j = 0; j < BN; ++j) {
            float p = __expf(sc[j] - mnew);
            sc[j] = p;
            ps += p;
        }
        lsum += ps;

        // ---- P @ V ----
#pragma unroll
        for (int j = 0; j < BN; ++j) {
            float p = sc[j];
#pragma unroll
            for (int dd = 0; dd < 8; ++dd) {
                float4 v = Vs[h][j][dd];
                acc[dd].x = fmaf(p, v.x, acc[dd].x);
                acc[dd].y = fmaf(p, v.y, acc[dd].y);
                acc[dd].z = fmaf(p, v.z, acc[dd].z);
                acc[dd].w = fmaf(p, v.w, acc[dd].w);
            }
        }
        asm volatile("bar.sync %0, %1;" :: "r"(1 + h), "r"(128) : "memory");
    }

    // ---- merge the two key-halves ----
    __syncthreads();
    if (h == 1) {
        stM[lt] = m;
        stL[lt] = lsum;
#pragma unroll
        for (int dd = 0; dd < 8; ++dd) stAcc[lt][dd] = acc[dd];
    }
    __syncthreads();
    if (h == 0) {
        float m2 = stM[lt], l2 = stL[lt];
        float mn = fmaxf(m, m2);
        float c1 = __expf(m - mn);
        float c2 = __expf(m2 - mn);
        float inv = 1.f / (lsum * c1 + l2 * c2);
        float4* Yp = (float4*)(d_y + ((size_t)b * LDIM + q0 + lt) * IDIM);
#pragma unroll
        for (int dd = 0; dd < 8; ++dd) {
            float4 a2 = stAcc[lt][dd];
            float4 o;
            o.x = (acc[dd].x * c1 + a2.x * c2) * inv;
            o.y = (acc[dd].y * c1 + a2.y * c2) * inv;
            o.z = (acc[dd].z * c1 + a2.z * c2) * inv;
            o.w = (acc[dd].w * c1 + a2.w * c2) * inv;
            Yp[dd] = o;
        }
    }
}

// ---------------------------------------------------------------------------
// Kernel 3: out[b,c,l] = sum_o W_w[c,o] * y[b,l,o] + W_b[c] + x[b,c,l]
// ---------------------------------------------------------------------------
__global__ __launch_bounds__(256) void out_kernel(
    const float* __restrict__ x,
    const float* __restrict__ W_w, const float* __restrict__ W_b,
    float* __restrict__ out)
{
    const int b  = blockIdx.y;
    const int l0 = blockIdx.x * 128;
    const int t  = threadIdx.x;

    __shared__ __align__(16) float ys[128][36];  // padded rows (9 float4)
    __shared__ float wt[CDIM][IDIM];
    __shared__ float wb[CDIM];

    const float4* Yg = (const float4*)(d_y + ((size_t)b * LDIM + l0) * IDIM);
    for (int idx = t; idx < 128 * 8; idx += 256) {
        int r = idx >> 3, cpos = idx & 7;
        ((float4*)ys[r])[cpos] = Yg[idx];
    }
    for (int idx = t; idx < CDIM * IDIM; idx += 256)
        ((float*)wt)[idx] = W_w[idx];
    if (t < CDIM) wb[t] = W_b[t];
    __syncthreads();

    for (int idx = t; idx < CDIM * 128; idx += 256) {
        int c = idx >> 7, l = idx & 127;
        float s0 = wb[c], s1 = 0.f;
#pragma unroll
        for (int o = 0; o < IDIM; o += 2) {
            s0 = fmaf(wt[c][o],     ys[l][o],     s0);
            s1 = fmaf(wt[c][o + 1], ys[l][o + 1], s1);
        }
        size_t gi = ((size_t)b * CDIM + c) * LDIM + l0 + l;
        out[gi] = s0 + s1 + x[gi];
    }
}

// ---------------------------------------------------------------------------
extern "C" void kernel_launch(void* const* d_in, const int* in_sizes, int n_in,
                              void* d_out, int out_size)
{
    const float* x    = (const float*)d_in[0];
    const float* g_w  = (const float*)d_in[1];
    const float* g_b  = (const float*)d_in[2];
    const float* th_w = (const float*)d_in[3];
    const float* th_b = (const float*)d_in[4];
    const float* ph_w = (const float*)d_in[5];
    const float* ph_b = (const float*)d_in[6];
    const float* W_w  = (const float*)d_in[7];
    const float* W_b  = (const float*)d_in[8];
    float* out = (float*)d_out;

    dim3 gp(LDIM / 128, BDIM);
    proj_kernel<<<gp, 256>>>(x, g_w, g_b, th_w, th_b, ph_w, ph_b);

    dim3 gf(LDIM / BM, BDIM);
    flash_kernel<<<gf, 256>>>();

    dim3 go(LDIM / 128, BDIM);
    out_kernel<<<go, 256>>>(x, W_w, W_b, out);
}